// round 4
// baseline (speedup 1.0000x reference)
#include <cuda_runtime.h>
#include <cmath>

#define N_NODES 12500
#define N_EDGES 200000
#define OUT_ELEMS (N_NODES * 64)

// shared memory layout (floats). stride 18: (18*w) mod 32 distinct for w=0..15
// -> conflict-free LDS.64 pair loads.
#define W2T_STRIDE 18
#define SM_W2T 0                          // 1024 rows * 18 = 18432 floats
#define SM_B2  (1024 * W2T_STRIDE)        // 18432 (1040: high half staggered +16)
#define SM_HP  (SM_B2 + 1040)             // 19472; 8 warps * 64 floats (32 ull each)
#define SM_TOT (SM_HP + 8 * 64)           // 19984 floats = 79936 bytes

__device__ int   g_src[N_EDGES];
__device__ int   g_dst[N_EDGES];
__device__ float g_counts[N_NODES];       // after h_kernel: 1/max(count,1)
__device__ float g_h[N_EDGES * 16];       // precomputed silu(ea@w1+b1)
__device__ int   g_is64;

typedef unsigned long long ull;

__device__ __forceinline__ ull pack2(float lo, float hi) {
    ull r;
    asm("mov.b64 %0, {%1, %2};" : "=l"(r) : "f"(lo), "f"(hi));
    return r;
}
__device__ __forceinline__ ull fma2(ull a, ull b, ull c) {
    ull d;
    asm("fma.rn.f32x2 %0, %1, %2, %3;" : "=l"(d) : "l"(a), "l"(b), "l"(c));
    return d;
}
__device__ __forceinline__ float pairsum(ull v) {
    float lo, hi;
    asm("mov.b64 {%0, %1}, %2;" : "=f"(lo), "=f"(hi) : "l"(v));
    return lo + hi;
}

// k1: detect edge_index dtype + zero output and counts
__global__ void zero_kernel(const unsigned* __restrict__ ei, float* __restrict__ out) {
    int i = blockIdx.x * blockDim.x + threadIdx.x;
    if (i == 0) {
        int ok = 1;
        for (int j = 0; j < 128; j++) ok &= (ei[2 * j + 1] == 0u);
        g_is64 = ok;
    }
    if (i < OUT_ELEMS) out[i] = 0.f;
    if (i < N_NODES) g_counts[i] = 0.f;
}

// k2: convert edge_index to int32 scratch + accumulate dst counts
__global__ void prep_kernel(const int* __restrict__ ei) {
    int i = blockIdx.x * blockDim.x + threadIdx.x;
    if (i < N_EDGES) {
        int s, d;
        if (g_is64) { s = ei[2 * i]; d = ei[2 * (N_EDGES + i)]; }
        else        { s = ei[i];     d = ei[N_EDGES + i]; }
        g_src[i] = s;
        g_dst[i] = d;
        atomicAdd(&g_counts[d], 1.f);
    }
}

// k3: h = silu(edge_attr @ w1 + b1); also inverts counts (prep already done)
__global__ void h_kernel(const float* __restrict__ ea,
                         const float* __restrict__ w1g,
                         const float* __restrict__ b1g) {
    __shared__ float sw[256], sb[16];
    if (threadIdx.x < 256) sw[threadIdx.x] = w1g[threadIdx.x];
    if (threadIdx.x < 16)  sb[threadIdx.x] = b1g[threadIdx.x];
    __syncthreads();
    int e = blockIdx.x * blockDim.x + threadIdx.x;
    if (e < N_NODES) g_counts[e] = 1.f / fmaxf(g_counts[e], 1.f);
    if (e >= N_EDGES) return;
    const float4* r = (const float4*)(ea + (size_t)e * 16);
    float4 v0 = r[0], v1 = r[1], v2 = r[2], v3 = r[3];
    float in[16] = {v0.x, v0.y, v0.z, v0.w, v1.x, v1.y, v1.z, v1.w,
                    v2.x, v2.y, v2.z, v2.w, v3.x, v3.y, v3.z, v3.w};
    float o[16];
    #pragma unroll
    for (int k = 0; k < 16; k++) {
        float t = sb[k];
        #pragma unroll
        for (int j = 0; j < 16; j++) t = fmaf(in[j], sw[j * 16 + k], t);
        o[k] = t / (1.f + __expf(-t));
    }
    float4* dst = (float4*)(g_h + (size_t)e * 16);
    dst[0] = make_float4(o[0], o[1], o[2], o[3]);
    dst[1] = make_float4(o[4], o[5], o[6], o[7]);
    dst[2] = make_float4(o[8], o[9], o[10], o[11]);
    dst[3] = make_float4(o[12], o[13], o[14], o[15]);
}

// ---------------------------------------------------------------------------
// k4: main conv. One warp processes 4 edges per pass; 2 blocks/SM (16 warps).
//   lane w = lane&15 owns output column w; lanes 0-15 -> weight blocks {0,1},
//   lanes 16-31 -> blocks {2,3}. k-contraction in packed fp32x2; h pairs live
//   in warp-private smem (broadcast reads), accumulators stay packed to the end.
// ---------------------------------------------------------------------------
__global__ void __launch_bounds__(256, 2) conv_kernel(
    const float*  __restrict__ node_attr,
    const float4* __restrict__ edge_sh4,
    const float*  __restrict__ w2,
    const float*  __restrict__ b2,
    float*        __restrict__ out)
{
    extern __shared__ float sm[];

    // stage w2 transposed to k-contiguous rows: w2t[j][k], j = b*256+u*16+w
    for (int i = threadIdx.x; i < 16 * 1024; i += 256) {
        int k = i >> 10, j = i & 1023;           // coalesced read of w2[k][j]
        sm[SM_W2T + j * W2T_STRIDE + k] = w2[i];
    }
    for (int i = threadIdx.x; i < 1024; i += 256)
        sm[SM_B2 + i + (i >= 512 ? 16 : 0)] = b2[i];   // stagger high half
    __syncthreads();

    const int lane = threadIdx.x & 31;
    const int wv   = lane & 15;
    const int hi16 = lane & 16;
    const int warpId = threadIdx.x >> 5;

    const float* pA  = sm + SM_W2T + ((hi16 ? 512 : 0) + wv) * W2T_STRIDE;
    const float* b2A = sm + SM_B2 + (hi16 ? 528 : 0) + wv;
    ull* hpw = (ull*)(sm + SM_HP) + warpId * 32;

    const float alpha = 0.17677669529663688f;    // 1/sqrt(32)
    const float inv3  = 0.57735026918962576f;    // 1/sqrt(3)

    const int warpsTotal = gridDim.x * (blockDim.x >> 5);
    const int gw = blockIdx.x * (blockDim.x >> 5) + warpId;

    const int hq = lane >> 3, hm = lane & 7;     // this lane's hp slot

    for (int p = gw; p < N_EDGES / 4; p += warpsTotal) {
        const int e0 = 4 * p;

        // stage h pairs for 4 edges into warp-private smem (1 ull per lane)
        __syncwarp();
        hpw[lane] = ((const ull*)g_h)[(size_t)(e0 + hq) * 8 + hm];
        __syncwarp();

        int d[4];
        float rA[4], rB1[4], rB2[4], rB3[4];
        #pragma unroll
        for (int q = 0; q < 4; q++) {
            d[q] = g_dst[e0 + q];
            int s = g_src[e0 + q];
            float4 sh = edge_sh4[e0 + q];
            const float* n = node_attr + (size_t)s * 64;
            float x0 = n[wv];
            float xa = n[16 + 3 * wv], xb = n[17 + 3 * wv], xc = n[18 + 3 * wv];
            if (hi16) { rA[q] = x0;        rB1[q] = xa; rB2[q] = xb; rB3[q] = xc; }
            else      { rA[q] = x0 * sh.x;
                        rB1[q] = fmaf(xa, sh.y, fmaf(xb, sh.z, xc * sh.w));
                        rB2[q] = 0.f; rB3[q] = 0.f; }
        }

        ull a0p[4], a1p[4], a2p[4], a3p[4];
        #pragma unroll
        for (int q = 0; q < 4; q++) a0p[q] = a1p[q] = a2p[q] = a3p[q] = 0ull;

        #pragma unroll 1
        for (int u = 0; u < 16; u++) {
            const int srcLane = u + hi16;
            ull s0p[4], s1p[4], s2p[4], s3p[4];
            #pragma unroll
            for (int q = 0; q < 4; q++) {
                float t0 = __shfl_sync(0xffffffffu, rA[q],  srcLane);
                float t1 = __shfl_sync(0xffffffffu, rB1[q], srcLane);
                float t2 = __shfl_sync(0xffffffffu, rB2[q], srcLane);
                float t3 = __shfl_sync(0xffffffffu, rB3[q], srcLane);
                s0p[q] = pack2(t0, t0);
                s1p[q] = pack2(t1, t1);
                s2p[q] = pack2(t2, t2);
                s3p[q] = pack2(t3, t3);
            }

            ull iA = pack2(b2A[u * 16], 0.f);
            ull iB = pack2(b2A[256 + u * 16], 0.f);
            ull accA[4] = {iA, iA, iA, iA};
            ull accB[4] = {iB, iB, iB, iB};

            const ull* qA = (const ull*)(pA + u * 16 * W2T_STRIDE);
            const ull* qB = qA + (256 * W2T_STRIDE / 2);
            #pragma unroll
            for (int m = 0; m < 8; m++) {
                ull wAm = qA[m];
                ull wBm = qB[m];
                #pragma unroll
                for (int q = 0; q < 4; q++) {
                    ull hv = hpw[q * 8 + m];
                    accA[q] = fma2(hv, wAm, accA[q]);
                    accB[q] = fma2(hv, wBm, accB[q]);
                }
            }
            #pragma unroll
            for (int q = 0; q < 4; q++) {
                a0p[q] = fma2(s0p[q], accA[q], a0p[q]);
                a1p[q] = fma2(s1p[q], accB[q], a1p[q]);
                a2p[q] = fma2(s2p[q], accB[q], a2p[q]);
                a3p[q] = fma2(s3p[q], accB[q], a3p[q]);
            }
        }

        // scatter-add with pre-folded alpha / count
        #pragma unroll
        for (int q = 0; q < 4; q++) {
            float a0 = pairsum(a0p[q]);
            float a1 = pairsum(a1p[q]);
            float scale = alpha * g_counts[d[q]];
            float* o = out + (size_t)d[q] * 64;
            if (!hi16) {
                atomicAdd(o + wv, scale * fmaf(inv3, a1, a0));
            } else {
                float a2 = pairsum(a2p[q]);
                float a3 = pairsum(a3p[q]);
                float4 sh = edge_sh4[e0 + q];
                atomicAdd(o + 16 + 3 * wv + 0, scale * fmaf(sh.y, a0, sh.x * a1));
                atomicAdd(o + 16 + 3 * wv + 1, scale * fmaf(sh.z, a0, sh.x * a2));
                atomicAdd(o + 16 + 3 * wv + 2, scale * fmaf(sh.w, a0, sh.x * a3));
            }
        }
    }
}

extern "C" void kernel_launch(void* const* d_in, const int* in_sizes, int n_in,
                              void* d_out, int out_size) {
    const float* node_attr  = (const float*)d_in[0];
    const void*  edge_index = d_in[1];
    const float* edge_attr  = (const float*)d_in[2];
    const float* edge_sh    = (const float*)d_in[3];
    const float* w1 = (const float*)d_in[4];
    const float* b1 = (const float*)d_in[5];
    const float* w2 = (const float*)d_in[6];
    const float* b2 = (const float*)d_in[7];
    float* out = (float*)d_out;

    cudaFuncSetAttribute(conv_kernel, cudaFuncAttributeMaxDynamicSharedMemorySize,
                         SM_TOT * (int)sizeof(float));

    int smCount = 148;
    cudaDeviceGetAttribute(&smCount, cudaDevAttrMultiProcessorCount, 0);

    zero_kernel<<<(OUT_ELEMS + 255) / 256, 256>>>((const unsigned*)edge_index, out);
    prep_kernel<<<(N_EDGES + 255) / 256, 256>>>((const int*)edge_index);
    h_kernel<<<(N_EDGES + 255) / 256, 256>>>(edge_attr, w1, b1);
    conv_kernel<<<2 * smCount, 256, SM_TOT * (int)sizeof(float)>>>(
        node_attr, (const float4*)edge_sh, w2, b2, out);
}

// round 5
// speedup vs baseline: 1.7080x; 1.7080x over previous
#include <cuda_runtime.h>
#include <cmath>

#define N_NODES 12500
#define N_EDGES 200000
#define OUT_ELEMS (N_NODES * 64)

// shared memory layout (floats). stride 20 floats = 80B: 16B-aligned rows so
// w2 rows load as LDS.128; bank pattern 20w mod 32 covers all 32 banks once
// per 8-lane phase -> conflict-free.
#define W2T_STRIDE 20
#define SM_W2T 0                          // 1024 rows * 20 = 20480 floats
#define SM_B2  (1024 * W2T_STRIDE)        // 20480 (high half staggered +16)
#define SM_TOT (SM_B2 + 1040)             // 21520 floats = 86080 bytes

__device__ int   g_src[N_EDGES];
__device__ int   g_dst[N_EDGES];
__device__ float g_counts[N_NODES];       // after h_kernel: 1/max(count,1)
__device__ float g_h[N_EDGES * 16];       // precomputed silu(ea@w1+b1)
__device__ int   g_is64;

typedef unsigned long long ull;

__device__ __forceinline__ ull pack2(float lo, float hi) {
    ull r;
    asm("mov.b64 %0, {%1, %2};" : "=l"(r) : "f"(lo), "f"(hi));
    return r;
}
__device__ __forceinline__ ull fma2(ull a, ull b, ull c) {
    ull d;
    asm("fma.rn.f32x2 %0, %1, %2, %3;" : "=l"(d) : "l"(a), "l"(b), "l"(c));
    return d;
}
__device__ __forceinline__ float pairsum(ull v) {
    float lo, hi;
    asm("mov.b64 {%0, %1}, %2;" : "=f"(lo), "=f"(hi) : "l"(v));
    return lo + hi;
}

// k1: detect edge_index dtype + zero output and counts
__global__ void zero_kernel(const unsigned* __restrict__ ei, float* __restrict__ out) {
    int i = blockIdx.x * blockDim.x + threadIdx.x;
    if (i == 0) {
        int ok = 1;
        for (int j = 0; j < 128; j++) ok &= (ei[2 * j + 1] == 0u);
        g_is64 = ok;
    }
    if (i < OUT_ELEMS) out[i] = 0.f;
    if (i < N_NODES) g_counts[i] = 0.f;
}

// k2: convert edge_index to int32 scratch + accumulate dst counts
__global__ void prep_kernel(const int* __restrict__ ei) {
    int i = blockIdx.x * blockDim.x + threadIdx.x;
    if (i < N_EDGES) {
        int s, d;
        if (g_is64) { s = ei[2 * i]; d = ei[2 * (N_EDGES + i)]; }
        else        { s = ei[i];     d = ei[N_EDGES + i]; }
        g_src[i] = s;
        g_dst[i] = d;
        atomicAdd(&g_counts[d], 1.f);
    }
}

// k3: h = silu(edge_attr @ w1 + b1); also inverts counts (prep already done)
__global__ void h_kernel(const float* __restrict__ ea,
                         const float* __restrict__ w1g,
                         const float* __restrict__ b1g) {
    __shared__ float sw[256], sb[16];
    if (threadIdx.x < 256) sw[threadIdx.x] = w1g[threadIdx.x];
    if (threadIdx.x < 16)  sb[threadIdx.x] = b1g[threadIdx.x];
    __syncthreads();
    int e = blockIdx.x * blockDim.x + threadIdx.x;
    if (e < N_NODES) g_counts[e] = 1.f / fmaxf(g_counts[e], 1.f);
    if (e >= N_EDGES) return;
    const float4* r = (const float4*)(ea + (size_t)e * 16);
    float4 v0 = r[0], v1 = r[1], v2 = r[2], v3 = r[3];
    float in[16] = {v0.x, v0.y, v0.z, v0.w, v1.x, v1.y, v1.z, v1.w,
                    v2.x, v2.y, v2.z, v2.w, v3.x, v3.y, v3.z, v3.w};
    float o[16];
    #pragma unroll
    for (int k = 0; k < 16; k++) {
        float t = sb[k];
        #pragma unroll
        for (int j = 0; j < 16; j++) t = fmaf(in[j], sw[j * 16 + k], t);
        o[k] = t / (1.f + __expf(-t));
    }
    float4* dst = (float4*)(g_h + (size_t)e * 16);
    dst[0] = make_float4(o[0], o[1], o[2], o[3]);
    dst[1] = make_float4(o[4], o[5], o[6], o[7]);
    dst[2] = make_float4(o[8], o[9], o[10], o[11]);
    dst[3] = make_float4(o[12], o[13], o[14], o[15]);
}

// ---------------------------------------------------------------------------
// k4: main conv. One warp processes 4 edges per pass; 192-thread blocks,
//   2 blocks/SM -> 12 warps/SM (3 per SMSP), reg cap 170 so the h pairs
//   (hp[4][8] = 64 regs) stay in registers. w2 rows load as LDS.128
//   (ulonglong2 = two packed f32x2 pairs, no repacking).
// ---------------------------------------------------------------------------
__global__ void __launch_bounds__(192, 2) conv_kernel(
    const float*  __restrict__ node_attr,
    const float4* __restrict__ edge_sh4,
    const float*  __restrict__ w2,
    const float*  __restrict__ b2,
    float*        __restrict__ out)
{
    extern __shared__ float sm[];

    // stage w2 transposed to k-contiguous rows: w2t[j][k], j = b*256+u*16+w
    for (int i = threadIdx.x; i < 16 * 1024; i += 192) {
        int k = i >> 10, j = i & 1023;           // coalesced read of w2[k][j]
        sm[SM_W2T + j * W2T_STRIDE + k] = w2[i];
    }
    for (int i = threadIdx.x; i < 1024; i += 192)
        sm[SM_B2 + i + (i >= 512 ? 16 : 0)] = b2[i];   // stagger high half
    __syncthreads();

    const int lane = threadIdx.x & 31;
    const int wv   = lane & 15;
    const int hi16 = lane & 16;
    const int warpId = threadIdx.x >> 5;

    const float* pA  = sm + SM_W2T + ((hi16 ? 512 : 0) + wv) * W2T_STRIDE;
    const float* b2A = sm + SM_B2 + (hi16 ? 528 : 0) + wv;

    const float alpha = 0.17677669529663688f;    // 1/sqrt(32)
    const float inv3  = 0.57735026918962576f;    // 1/sqrt(3)

    const int warpsTotal = gridDim.x * 6;
    const int gw = blockIdx.x * 6 + warpId;

    for (int p = gw; p < N_EDGES / 4; p += warpsTotal) {
        const int e0 = 4 * p;

        // h pairs for 4 edges: 4 x LDG.128 per edge, stays in registers
        ull hp[4][8];
        #pragma unroll
        for (int q = 0; q < 4; q++) {
            const ulonglong2* gh = (const ulonglong2*)(g_h + (size_t)(e0 + q) * 16);
            ulonglong2 ga = gh[0], gb = gh[1], gc = gh[2], gd = gh[3];
            hp[q][0] = ga.x; hp[q][1] = ga.y; hp[q][2] = gb.x; hp[q][3] = gb.y;
            hp[q][4] = gc.x; hp[q][5] = gc.y; hp[q][6] = gd.x; hp[q][7] = gd.y;
        }

        int d[4];
        float rA[4], rB1[4], rB2[4], rB3[4];
        #pragma unroll
        for (int q = 0; q < 4; q++) {
            d[q] = g_dst[e0 + q];
            int s = g_src[e0 + q];
            float4 sh = edge_sh4[e0 + q];
            const float* n = node_attr + (size_t)s * 64;
            float x0 = n[wv];
            float xa = n[16 + 3 * wv], xb = n[17 + 3 * wv], xc = n[18 + 3 * wv];
            if (hi16) { rA[q] = x0;        rB1[q] = xa; rB2[q] = xb; rB3[q] = xc; }
            else      { rA[q] = x0 * sh.x;
                        rB1[q] = fmaf(xa, sh.y, fmaf(xb, sh.z, xc * sh.w));
                        rB2[q] = 0.f; rB3[q] = 0.f; }
        }

        ull a0p[4], a1p[4], a2p[4], a3p[4];
        #pragma unroll
        for (int q = 0; q < 4; q++) a0p[q] = a1p[q] = a2p[q] = a3p[q] = 0ull;

        #pragma unroll 1
        for (int u = 0; u < 16; u++) {
            const int srcLane = u + hi16;
            ull s0p[4], s1p[4], s2p[4], s3p[4];
            #pragma unroll
            for (int q = 0; q < 4; q++) {
                float t0 = __shfl_sync(0xffffffffu, rA[q],  srcLane);
                float t1 = __shfl_sync(0xffffffffu, rB1[q], srcLane);
                float t2 = __shfl_sync(0xffffffffu, rB2[q], srcLane);
                float t3 = __shfl_sync(0xffffffffu, rB3[q], srcLane);
                s0p[q] = pack2(t0, t0);
                s1p[q] = pack2(t1, t1);
                s2p[q] = pack2(t2, t2);
                s3p[q] = pack2(t3, t3);
            }

            ull iA = pack2(b2A[u * 16], 0.f);
            ull iB = pack2(b2A[256 * 16 / 16 * 16 + u * 16 - 256 * 16 + 256], 0.f); // placeholder; fixed below
            // (compute properly:)
            iB = pack2(b2A[256 + u * 16], 0.f);
            ull accA[4] = {iA, iA, iA, iA};
            ull accB[4] = {iB, iB, iB, iB};

            const ulonglong2* qA = (const ulonglong2*)(pA + u * 16 * W2T_STRIDE);
            const ulonglong2* qB = (const ulonglong2*)(pA + (256 + u * 16) * W2T_STRIDE);
            #pragma unroll
            for (int j = 0; j < 4; j++) {
                ulonglong2 wA = qA[j];
                ulonglong2 wB = qB[j];
                #pragma unroll
                for (int q = 0; q < 4; q++) {
                    accA[q] = fma2(hp[q][2 * j],     wA.x, accA[q]);
                    accA[q] = fma2(hp[q][2 * j + 1], wA.y, accA[q]);
                    accB[q] = fma2(hp[q][2 * j],     wB.x, accB[q]);
                    accB[q] = fma2(hp[q][2 * j + 1], wB.y, accB[q]);
                }
            }
            #pragma unroll
            for (int q = 0; q < 4; q++) {
                a0p[q] = fma2(s0p[q], accA[q], a0p[q]);
                a1p[q] = fma2(s1p[q], accB[q], a1p[q]);
                a2p[q] = fma2(s2p[q], accB[q], a2p[q]);
                a3p[q] = fma2(s3p[q], accB[q], a3p[q]);
            }
        }

        // scatter-add with pre-folded alpha / count
        #pragma unroll
        for (int q = 0; q < 4; q++) {
            float a0 = pairsum(a0p[q]);
            float a1 = pairsum(a1p[q]);
            float scale = alpha * g_counts[d[q]];
            float* o = out + (size_t)d[q] * 64;
            if (!hi16) {
                atomicAdd(o + wv, scale * fmaf(inv3, a1, a0));
            } else {
                float a2 = pairsum(a2p[q]);
                float a3 = pairsum(a3p[q]);
                float4 sh = edge_sh4[e0 + q];
                atomicAdd(o + 16 + 3 * wv + 0, scale * fmaf(sh.y, a0, sh.x * a1));
                atomicAdd(o + 16 + 3 * wv + 1, scale * fmaf(sh.z, a0, sh.x * a2));
                atomicAdd(o + 16 + 3 * wv + 2, scale * fmaf(sh.w, a0, sh.x * a3));
            }
        }
    }
}

extern "C" void kernel_launch(void* const* d_in, const int* in_sizes, int n_in,
                              void* d_out, int out_size) {
    const float* node_attr  = (const float*)d_in[0];
    const void*  edge_index = d_in[1];
    const float* edge_attr  = (const float*)d_in[2];
    const float* edge_sh    = (const float*)d_in[3];
    const float* w1 = (const float*)d_in[4];
    const float* b1 = (const float*)d_in[5];
    const float* w2 = (const float*)d_in[6];
    const float* b2 = (const float*)d_in[7];
    float* out = (float*)d_out;

    cudaFuncSetAttribute(conv_kernel, cudaFuncAttributeMaxDynamicSharedMemorySize,
                         SM_TOT * (int)sizeof(float));

    int smCount = 148;
    cudaDeviceGetAttribute(&smCount, cudaDevAttrMultiProcessorCount, 0);

    zero_kernel<<<(OUT_ELEMS + 255) / 256, 256>>>((const unsigned*)edge_index, out);
    prep_kernel<<<(N_EDGES + 255) / 256, 256>>>((const int*)edge_index);
    h_kernel<<<(N_EDGES + 255) / 256, 256>>>(edge_attr, w1, b1);
    conv_kernel<<<2 * smCount, 192, SM_TOT * (int)sizeof(float)>>>(
        node_attr, (const float4*)edge_sh, w2, b2, out);
}

// round 7
// speedup vs baseline: 3.0043x; 1.7589x over previous
#include <cuda_runtime.h>
#include <cstdint>
#include <cmath>

#define N_NODES 12500
#define N_EDGES 200000
#define OUT_ELEMS (N_NODES * 64)
#define N_TILES (N_EDGES / 16)        // 12500 tiles of 16 edges, exact
#define A_STRIDE 24                    // padded A row: h[16] | 1 | 0*7

// smem layout (floats)
#define B_ROW 1032                     // 1024 + 8 pad -> conflict-free B frags
#define SM_B   0                       // 24 * 1032 = 24768
#define SM_CS  (24 * B_ROW)
#define CS_WARP 1632                   // 6*256 coeff + 64 sh + 16 scale + 16 dst
#define SM_BYTES ((SM_CS + 16 * CS_WARP) * 4)   // 203520 bytes

__device__ int   g_src[N_EDGES];
__device__ int   g_dst[N_EDGES];
__device__ float g_counts[N_NODES];        // after h_kernel: 1/max(count,1)
__device__ float g_h2[(size_t)N_EDGES * A_STRIDE];  // tf32 A rows
__device__ int   g_is64;

__device__ __forceinline__ float to_tf32(float x) {
    uint32_t u; asm("cvt.rna.tf32.f32 %0, %1;" : "=r"(u) : "f"(x));
    return __uint_as_float(u);
}

// m16n8k8 tf32 HMMA, D accumulates in place
__device__ __forceinline__ void mma8(float* d, const uint32_t* a, uint32_t b0, uint32_t b1) {
    asm volatile("mma.sync.aligned.m16n8k8.row.col.f32.tf32.tf32.f32 "
        "{%0,%1,%2,%3}, {%4,%5,%6,%7}, {%8,%9}, {%0,%1,%2,%3};"
        : "+f"(d[0]), "+f"(d[1]), "+f"(d[2]), "+f"(d[3])
        : "r"(a[0]), "r"(a[1]), "r"(a[2]), "r"(a[3]), "r"(b0), "r"(b1));
}

// k1: detect edge_index dtype + zero output and counts
__global__ void zero_kernel(const unsigned* __restrict__ ei, float* __restrict__ out) {
    int i = blockIdx.x * blockDim.x + threadIdx.x;
    if (i == 0) {
        int ok = 1;
        for (int j = 0; j < 128; j++) ok &= (ei[2 * j + 1] == 0u);
        g_is64 = ok;
    }
    if (i < OUT_ELEMS) out[i] = 0.f;
    if (i < N_NODES) g_counts[i] = 0.f;
}

// k2: edge_index -> int32, count dsts
__global__ void prep_kernel(const int* __restrict__ ei) {
    int i = blockIdx.x * blockDim.x + threadIdx.x;
    if (i < N_EDGES) {
        int s, d;
        if (g_is64) { s = ei[2 * i]; d = ei[2 * (N_EDGES + i)]; }
        else        { s = ei[i];     d = ei[N_EDGES + i]; }
        g_src[i] = s; g_dst[i] = d;
        atomicAdd(&g_counts[d], 1.f);
    }
}

// k3: A rows = [tf32(silu(ea@w1+b1)) | 1 | 0*7]; also inverts counts
__global__ void h_kernel(const float* __restrict__ ea,
                         const float* __restrict__ w1g,
                         const float* __restrict__ b1g) {
    __shared__ float sw[256], sb[16];
    if (threadIdx.x < 256) sw[threadIdx.x] = w1g[threadIdx.x];
    if (threadIdx.x < 16)  sb[threadIdx.x] = b1g[threadIdx.x];
    __syncthreads();
    int e = blockIdx.x * blockDim.x + threadIdx.x;
    if (e < N_NODES) g_counts[e] = 1.f / fmaxf(g_counts[e], 1.f);
    if (e >= N_EDGES) return;
    const float4* r = (const float4*)(ea + (size_t)e * 16);
    float4 v0 = r[0], v1 = r[1], v2 = r[2], v3 = r[3];
    float in[16] = {v0.x, v0.y, v0.z, v0.w, v1.x, v1.y, v1.z, v1.w,
                    v2.x, v2.y, v2.z, v2.w, v3.x, v3.y, v3.z, v3.w};
    float o[16];
    #pragma unroll
    for (int k = 0; k < 16; k++) {
        float t = sb[k];
        #pragma unroll
        for (int j = 0; j < 16; j++) t = fmaf(in[j], sw[j * 16 + k], t);
        o[k] = to_tf32(t / (1.f + __expf(-t)));
    }
    float4* dst = (float4*)(g_h2 + (size_t)e * A_STRIDE);
    dst[0] = make_float4(o[0], o[1], o[2], o[3]);
    dst[1] = make_float4(o[4], o[5], o[6], o[7]);
    dst[2] = make_float4(o[8], o[9], o[10], o[11]);
    dst[3] = make_float4(o[12], o[13], o[14], o[15]);
    dst[4] = make_float4(1.f, 0.f, 0.f, 0.f);
    dst[5] = make_float4(0.f, 0.f, 0.f, 0.f);
}

// ---------------------------------------------------------------------------
// k4: conv. One warp = 16 edges. W = A@B via m16n8k8 tf32 mma.sync; D rows =
// edges so the u-contraction is thread-local against smem coefficients.
// ---------------------------------------------------------------------------
__global__ void __launch_bounds__(512, 1) conv_kernel(
    const float*  __restrict__ node_attr,
    const float4* __restrict__ edge_sh4,
    const float*  __restrict__ w2,
    const float*  __restrict__ b2,
    float*        __restrict__ out)
{
    extern __shared__ float sm[];
    const int tid = threadIdx.x, lane = tid & 31, warp = tid >> 5;
    const int g = lane >> 2, tig = lane & 3;

    // stage B = w2_aug (tf32): rows 0-15 = w2[k], row 16 = b2, rows 17-23 = 0
    for (int i = tid; i < 24 * 1024; i += 512) {
        int k = i >> 10, j = i & 1023;
        float v = (k < 16) ? w2[i] : (k == 16 ? b2[j] : 0.f);
        sm[SM_B + k * B_ROW + j] = to_tf32(v);
    }
    __syncthreads();

    float* cs = sm + SM_CS + warp * CS_WARP;
    const int eL = lane & 15, u0 = (lane >> 4) * 8;
    const float alpha = 0.17677669529663688f;   // 1/sqrt(32)
    const float inv3  = 0.57735026918962576f;   // 1/sqrt(3)

    const uint32_t* Ag = (const uint32_t*)g_h2;
    const uint32_t* Bb = (const uint32_t*)(sm + SM_B) + tig * B_ROW + g;

    for (int t = blockIdx.x * 16 + warp; t < N_TILES; t += gridDim.x * 16) {
        const int e0 = t * 16;

        // ---- coefficient staging (warp-private smem) ----
        __syncwarp();
        {
            int eg = e0 + eL;
            int sn = g_src[eg];
            float4 sh = edge_sh4[eg];
            const float* na = node_attr + (size_t)sn * 64;
            #pragma unroll
            for (int i = 0; i < 8; i++) {
                int u = u0 + i;
                float x0 = na[u];
                float xa = na[16 + 3*u], xb = na[17 + 3*u], xc = na[18 + 3*u];
                cs[       u*16 + eL] = x0 * sh.x;                                   // c0
                cs[256  + u*16 + eL] = inv3 * (xa*sh.y + xb*sh.z + xc*sh.w);        // z
                cs[512  + u*16 + eL] = x0;                                          // x0
                cs[768  + u*16 + eL] = sh.x * xa;                                   // y0*x1a
                cs[1024 + u*16 + eL] = sh.x * xb;                                   // y0*x1b
                cs[1280 + u*16 + eL] = sh.x * xc;                                   // y0*x1c
            }
            if (u0 == 0) {
                ((float4*)(cs + 1536))[eL] = sh;
                int dn = g_dst[eg];
                cs[1600 + eL] = alpha * g_counts[dn];
                ((int*)(cs + 1616))[eL] = dn;
            }
        }
        __syncwarp();

        // ---- A fragments: 16 edges x 24 k, 3 k-steps ----
        uint32_t a[3][4];
        #pragma unroll
        for (int s = 0; s < 3; s++) {
            a[s][0] = Ag[(size_t)(e0 + g)     * A_STRIDE + s*8 + tig];
            a[s][1] = Ag[(size_t)(e0 + g + 8) * A_STRIDE + s*8 + tig];
            a[s][2] = Ag[(size_t)(e0 + g)     * A_STRIDE + s*8 + tig + 4];
            a[s][3] = Ag[(size_t)(e0 + g + 8) * A_STRIDE + s*8 + tig + 4];
        }

        float o0[2][2][2]  = {}, tAc[2][2][2] = {};
        float oA[2][2][2]  = {}, oB[2][2][2]  = {}, oC[2][2][2] = {};

#define MMA_PAIR(BBASE, U) \
        float d0[4] = {0.f,0.f,0.f,0.f}, d1[4] = {0.f,0.f,0.f,0.f}; \
        { const uint32_t* bp = Bb + (BBASE) + (U) * 16; \
          _Pragma("unroll") \
          for (int s = 0; s < 3; s++) { \
            uint32_t b00 = bp[s*8*B_ROW],     b01 = bp[(s*8+4)*B_ROW]; \
            uint32_t b10 = bp[s*8*B_ROW + 8], b11 = bp[(s*8+4)*B_ROW + 8]; \
            mma8(d0, a[s], b00, b01); \
            mma8(d1, a[s], b10, b11); \
          } }

#define ACC1(ACC, CBASE, U) { \
        float cg = cs[(CBASE) + (U)*16 + g], ch = cs[(CBASE) + (U)*16 + g + 8]; \
        ACC[0][0][0] += cg*d0[0]; ACC[0][0][1] += cg*d0[1]; \
        ACC[1][0][0] += ch*d0[2]; ACC[1][0][1] += ch*d0[3]; \
        ACC[0][1][0] += cg*d1[0]; ACC[0][1][1] += cg*d1[1]; \
        ACC[1][1][0] += ch*d1[2]; ACC[1][1][1] += ch*d1[3]; }

        #pragma unroll 4
        for (int u = 0; u < 16; u++) { MMA_PAIR(0, u)    ACC1(o0,  0,    u) }
        #pragma unroll 4
        for (int u = 0; u < 16; u++) { MMA_PAIR(256, u)  ACC1(o0,  256,  u) }
        #pragma unroll 4
        for (int u = 0; u < 16; u++) { MMA_PAIR(512, u)  ACC1(tAc, 512,  u) }
        #pragma unroll 4
        for (int u = 0; u < 16; u++) { MMA_PAIR(768, u)
            ACC1(oA, 768, u) ACC1(oB, 1024, u) ACC1(oC, 1280, u) }
#undef MMA_PAIR
#undef ACC1

        // ---- scatter: out0 at cols [0,16), out1 at 16 + 3w + i ----
        #pragma unroll
        for (int r2 = 0; r2 < 2; r2++) {
            int e = g + r2 * 8;
            float4 sh = ((float4*)(cs + 1536))[e];
            float sca = cs[1600 + e];
            int dn = ((int*)(cs + 1616))[e];
            float* o = out + (size_t)dn * 64;
            atomicAdd(o + 2*tig,         sca * o0[r2][0][0]);
            atomicAdd(o + 2*tig + 1,     sca * o0[r2][0][1]);
            atomicAdd(o + 8 + 2*tig,     sca * o0[r2][1][0]);
            atomicAdd(o + 8 + 2*tig + 1, sca * o0[r2][1][1]);
            #pragma unroll
            for (int wh = 0; wh < 2; wh++)
            #pragma unroll
            for (int c = 0; c < 2; c++) {
                int w = wh*8 + 2*tig + c;
                float tv = tAc[r2][wh][c];
                atomicAdd(o + 16 + 3*w,     sca * (sh.y*tv + oA[r2][wh][c]));
                atomicAdd(o + 16 + 3*w + 1, sca * (sh.z*tv + oB[r2][wh][c]));
                atomicAdd(o + 16 + 3*w + 2, sca * (sh.w*tv + oC[r2][wh][c]));
            }
        }
    }
}

extern "C" void kernel_launch(void* const* d_in, const int* in_sizes, int n_in,
                              void* d_out, int out_size) {
    const float* node_attr  = (const float*)d_in[0];
    const void*  edge_index = d_in[1];
    const float* edge_attr  = (const float*)d_in[2];
    const float* edge_sh    = (const float*)d_in[3];
    const float* w1 = (const float*)d_in[4];
    const float* b1 = (const float*)d_in[5];
    const float* w2 = (const float*)d_in[6];
    const float* b2 = (const float*)d_in[7];
    float* out = (float*)d_out;

    cudaFuncSetAttribute(conv_kernel, cudaFuncAttributeMaxDynamicSharedMemorySize, SM_BYTES);

    int smCount = 148;
    cudaDeviceGetAttribute(&smCount, cudaDevAttrMultiProcessorCount, 0);

    zero_kernel<<<(OUT_ELEMS + 255) / 256, 256>>>((const unsigned*)edge_index, out);
    prep_kernel<<<(N_EDGES + 255) / 256, 256>>>((const int*)edge_index);
    h_kernel<<<(N_EDGES + 255) / 256, 256>>>(edge_attr, w1, b1);
    conv_kernel<<<smCount, 512, SM_BYTES>>>(node_attr, (const float4*)edge_sh,
                                            w2, b2, out);
}

// round 8
// speedup vs baseline: 3.1379x; 1.0445x over previous
#include <cuda_runtime.h>
#include <cstdint>
#include <cmath>

#define N_NODES 12500
#define N_EDGES 200000
#define OUT_ELEMS (N_NODES * 64)
#define N_TILES (N_EDGES / 16)        // 12500 tiles of 16 edges, exact
#define A_STRIDE 24                    // padded A row: h[16] | 1 | 0*7

// smem layout (floats)
#define BP_WORDS (4 * 16 * 32 * 12)    // 24576: fragment-packed B
#define SM_BP  0
#define SM_CS  BP_WORDS
#define CS_WARP 1632                   // 6*256 coeff + 64 sh + 16 scale + 16 dst
#define SM_BYTES ((SM_CS + 16 * CS_WARP) * 4)   // 202752 bytes

__device__ int   g_src[N_EDGES];
__device__ int   g_dst[N_EDGES];
__device__ float g_counts[N_NODES];        // after h_kernel: 1/max(count,1)
__device__ float g_h2[(size_t)N_EDGES * A_STRIDE];  // tf32 A rows
__device__ float g_Bpack[BP_WORDS];        // fragment-order packed B (tf32)
__device__ int   g_is64;

__device__ __forceinline__ float to_tf32(float x) {
    uint32_t u; asm("cvt.rna.tf32.f32 %0, %1;" : "=r"(u) : "f"(x));
    return __uint_as_float(u);
}

// m16n8k8 tf32 HMMA, D accumulates in place
__device__ __forceinline__ void mma8(float* d, const uint32_t* a, uint32_t b0, uint32_t b1) {
    asm volatile("mma.sync.aligned.m16n8k8.row.col.f32.tf32.tf32.f32 "
        "{%0,%1,%2,%3}, {%4,%5,%6,%7}, {%8,%9}, {%0,%1,%2,%3};"
        : "+f"(d[0]), "+f"(d[1]), "+f"(d[2]), "+f"(d[3])
        : "r"(a[0]), "r"(a[1]), "r"(a[2]), "r"(a[3]), "r"(b0), "r"(b1));
}

// k1: detect dtype, zero out/counts, build fragment-packed B
// Bpack[((blk*16+u)*32 + lane)*12 + s*4 + r]:
//   col = blk*256 + u*16 + (lane>>2) + (r>=2 ? 8 : 0)
//   k   = s*8 + (lane&3) + ((r&1) ? 4 : 0)
//   val = k<16 ? w2[k,col] : k==16 ? b2[col] : 0     (tf32)
__global__ void zero_kernel(const unsigned* __restrict__ ei, float* __restrict__ out,
                            const float* __restrict__ w2, const float* __restrict__ b2) {
    int i = blockIdx.x * blockDim.x + threadIdx.x;
    if (i == 0) {
        int ok = 1;
        for (int j = 0; j < 128; j++) ok &= (ei[2 * j + 1] == 0u);
        g_is64 = ok;
    }
    if (i < OUT_ELEMS) out[i] = 0.f;
    if (i < N_NODES) g_counts[i] = 0.f;
    if (i < BP_WORDS) {
        int m = i % 12, lane = (i / 12) & 31, bu = i / (12 * 32);
        int s = m >> 2, r = m & 3;
        int col = (bu >> 4) * 256 + (bu & 15) * 16 + (lane >> 2) + ((r & 2) ? 8 : 0);
        int k = s * 8 + (lane & 3) + ((r & 1) ? 4 : 0);
        float v = (k < 16) ? w2[k * 1024 + col] : (k == 16 ? b2[col] : 0.f);
        g_Bpack[i] = to_tf32(v);
    }
}

// k2: edge_index -> int32, count dsts
__global__ void prep_kernel(const int* __restrict__ ei) {
    int i = blockIdx.x * blockDim.x + threadIdx.x;
    if (i < N_EDGES) {
        int s, d;
        if (g_is64) { s = ei[2 * i]; d = ei[2 * (N_EDGES + i)]; }
        else        { s = ei[i];     d = ei[N_EDGES + i]; }
        g_src[i] = s; g_dst[i] = d;
        atomicAdd(&g_counts[d], 1.f);
    }
}

// k3: A rows = [tf32(silu(ea@w1+b1)) | 1 | 0*7]; also inverts counts
__global__ void h_kernel(const float* __restrict__ ea,
                         const float* __restrict__ w1g,
                         const float* __restrict__ b1g) {
    __shared__ float sw[256], sb[16];
    if (threadIdx.x < 256) sw[threadIdx.x] = w1g[threadIdx.x];
    if (threadIdx.x < 16)  sb[threadIdx.x] = b1g[threadIdx.x];
    __syncthreads();
    int e = blockIdx.x * blockDim.x + threadIdx.x;
    if (e < N_NODES) g_counts[e] = 1.f / fmaxf(g_counts[e], 1.f);
    if (e >= N_EDGES) return;
    const float4* r = (const float4*)(ea + (size_t)e * 16);
    float4 v0 = r[0], v1 = r[1], v2 = r[2], v3 = r[3];
    float in[16] = {v0.x, v0.y, v0.z, v0.w, v1.x, v1.y, v1.z, v1.w,
                    v2.x, v2.y, v2.z, v2.w, v3.x, v3.y, v3.z, v3.w};
    float o[16];
    #pragma unroll
    for (int k = 0; k < 16; k++) {
        float t = sb[k];
        #pragma unroll
        for (int j = 0; j < 16; j++) t = fmaf(in[j], sw[j * 16 + k], t);
        o[k] = to_tf32(t / (1.f + __expf(-t)));
    }
    float4* dst = (float4*)(g_h2 + (size_t)e * A_STRIDE);
    dst[0] = make_float4(o[0], o[1], o[2], o[3]);
    dst[1] = make_float4(o[4], o[5], o[6], o[7]);
    dst[2] = make_float4(o[8], o[9], o[10], o[11]);
    dst[3] = make_float4(o[12], o[13], o[14], o[15]);
    dst[4] = make_float4(1.f, 0.f, 0.f, 0.f);
    dst[5] = make_float4(0.f, 0.f, 0.f, 0.f);
}

// ---------------------------------------------------------------------------
// k4: conv. One warp = 16 edges. W = A@B via m16n8k8 tf32 mma.sync with
// fragment-packed B (3 x LDS.128 per MMA pair); u-contraction thread-local.
// ---------------------------------------------------------------------------
__global__ void __launch_bounds__(512, 1) conv_kernel(
    const float*  __restrict__ node_attr,
    const float4* __restrict__ edge_sh4,
    float*        __restrict__ out)
{
    extern __shared__ float sm[];
    const int tid = threadIdx.x, lane = tid & 31, warp = tid >> 5;
    const int g = lane >> 2, tig = lane & 3;

    // stage fragment-packed B (96 KB)
    for (int i = tid; i < BP_WORDS / 4; i += 512)
        ((float4*)sm)[i] = ((const float4*)g_Bpack)[i];
    __syncthreads();

    float* cs = sm + SM_CS + warp * CS_WARP;
    const int eL = lane & 15, u0 = (lane >> 4) * 8;
    const float alpha = 0.17677669529663688f;   // 1/sqrt(32)
    const float inv3  = 0.57735026918962576f;   // 1/sqrt(3)

    const uint32_t* Ag = (const uint32_t*)g_h2;
    const float4* Bp = (const float4*)sm + lane * 3;   // + (blk*16+u)*96

    for (int t = blockIdx.x * 16 + warp; t < N_TILES; t += gridDim.x * 16) {
        const int e0 = t * 16;

        // ---- coefficient staging (warp-private smem) ----
        __syncwarp();
        {
            int eg = e0 + eL;
            int sn = g_src[eg];
            float4 sh = edge_sh4[eg];
            const float* na = node_attr + (size_t)sn * 64;
            #pragma unroll
            for (int i = 0; i < 8; i++) {
                int u = u0 + i;
                float x0 = na[u];
                float xa = na[16 + 3*u], xb = na[17 + 3*u], xc = na[18 + 3*u];
                cs[       u*16 + eL] = x0 * sh.x;                                   // c0
                cs[256  + u*16 + eL] = inv3 * (xa*sh.y + xb*sh.z + xc*sh.w);        // z
                cs[512  + u*16 + eL] = x0;                                          // x0
                cs[768  + u*16 + eL] = sh.x * xa;                                   // y0*x1a
                cs[1024 + u*16 + eL] = sh.x * xb;                                   // y0*x1b
                cs[1280 + u*16 + eL] = sh.x * xc;                                   // y0*x1c
            }
            if (u0 == 0) {
                ((float4*)(cs + 1536))[eL] = sh;
                int dn = g_dst[eg];
                cs[1600 + eL] = alpha * g_counts[dn];
                ((int*)(cs + 1616))[eL] = dn;
            }
        }
        __syncwarp();

        // ---- A fragments: 16 edges x 24 k, 3 k-steps ----
        uint32_t a[3][4];
        #pragma unroll
        for (int s = 0; s < 3; s++) {
            a[s][0] = Ag[(size_t)(e0 + g)     * A_STRIDE + s*8 + tig];
            a[s][1] = Ag[(size_t)(e0 + g + 8) * A_STRIDE + s*8 + tig];
            a[s][2] = Ag[(size_t)(e0 + g)     * A_STRIDE + s*8 + tig + 4];
            a[s][3] = Ag[(size_t)(e0 + g + 8) * A_STRIDE + s*8 + tig + 4];
        }

        float o0[2][2][2]  = {}, tAc[2][2][2] = {};
        float oA[2][2][2]  = {}, oB[2][2][2]  = {}, oC[2][2][2] = {};

#define MMA_PAIR(BLK, U) \
        float d0[4] = {0.f,0.f,0.f,0.f}, d1[4] = {0.f,0.f,0.f,0.f}; \
        { const float4* bp = Bp + ((BLK)*16 + (U)) * 96; \
          _Pragma("unroll") \
          for (int s = 0; s < 3; s++) { \
            float4 bv = bp[s]; \
            mma8(d0, a[s], __float_as_uint(bv.x), __float_as_uint(bv.y)); \
            mma8(d1, a[s], __float_as_uint(bv.z), __float_as_uint(bv.w)); \
          } }

#define ACC1(ACC, CBASE, U) { \
        float cg = cs[(CBASE) + (U)*16 + g], ch = cs[(CBASE) + (U)*16 + g + 8]; \
        ACC[0][0][0] += cg*d0[0]; ACC[0][0][1] += cg*d0[1]; \
        ACC[1][0][0] += ch*d0[2]; ACC[1][0][1] += ch*d0[3]; \
        ACC[0][1][0] += cg*d1[0]; ACC[0][1][1] += cg*d1[1]; \
        ACC[1][1][0] += ch*d1[2]; ACC[1][1][1] += ch*d1[3]; }

        #pragma unroll 4
        for (int u = 0; u < 16; u++) { MMA_PAIR(0, u) ACC1(o0,  0,    u) }
        #pragma unroll 4
        for (int u = 0; u < 16; u++) { MMA_PAIR(1, u) ACC1(o0,  256,  u) }
        #pragma unroll 4
        for (int u = 0; u < 16; u++) { MMA_PAIR(2, u) ACC1(tAc, 512,  u) }
        #pragma unroll 4
        for (int u = 0; u < 16; u++) { MMA_PAIR(3, u)
            ACC1(oA, 768, u) ACC1(oB, 1024, u) ACC1(oC, 1280, u) }
#undef MMA_PAIR
#undef ACC1

        // ---- scatter: out0 at cols [0,16), out1 at 16 + 3w + i ----
        #pragma unroll
        for (int r2 = 0; r2 < 2; r2++) {
            int e = g + r2 * 8;
            float4 sh = ((float4*)(cs + 1536))[e];
            float sca = cs[1600 + e];
            int dn = ((int*)(cs + 1616))[e];
            float* o = out + (size_t)dn * 64;
            atomicAdd(o + 2*tig,         sca * o0[r2][0][0]);
            atomicAdd(o + 2*tig + 1,     sca * o0[r2][0][1]);
            atomicAdd(o + 8 + 2*tig,     sca * o0[r2][1][0]);
            atomicAdd(o + 8 + 2*tig + 1, sca * o0[r2][1][1]);
            #pragma unroll
            for (int wh = 0; wh < 2; wh++)
            #pragma unroll
            for (int c = 0; c < 2; c++) {
                int w = wh*8 + 2*tig + c;
                float tv = tAc[r2][wh][c];
                atomicAdd(o + 16 + 3*w,     sca * (sh.y*tv + oA[r2][wh][c]));
                atomicAdd(o + 16 + 3*w + 1, sca * (sh.z*tv + oB[r2][wh][c]));
                atomicAdd(o + 16 + 3*w + 2, sca * (sh.w*tv + oC[r2][wh][c]));
            }
        }
    }
}

extern "C" void kernel_launch(void* const* d_in, const int* in_sizes, int n_in,
                              void* d_out, int out_size) {
    const float* node_attr  = (const float*)d_in[0];
    const void*  edge_index = d_in[1];
    const float* edge_attr  = (const float*)d_in[2];
    const float* edge_sh    = (const float*)d_in[3];
    const float* w1 = (const float*)d_in[4];
    const float* b1 = (const float*)d_in[5];
    const float* w2 = (const float*)d_in[6];
    const float* b2 = (const float*)d_in[7];
    float* out = (float*)d_out;

    cudaFuncSetAttribute(conv_kernel, cudaFuncAttributeMaxDynamicSharedMemorySize, SM_BYTES);

    int smCount = 148;
    cudaDeviceGetAttribute(&smCount, cudaDevAttrMultiProcessorCount, 0);

    zero_kernel<<<(OUT_ELEMS + 255) / 256, 256>>>((const unsigned*)edge_index, out, w2, b2);
    prep_kernel<<<(N_EDGES + 255) / 256, 256>>>((const int*)edge_index);
    h_kernel<<<(N_EDGES + 255) / 256, 256>>>(edge_attr, w1, b1);
    conv_kernel<<<smCount, 512, SM_BYTES>>>(node_attr, (const float4*)edge_sh, out);
}

// round 9
// speedup vs baseline: 3.3776x; 1.0764x over previous
#include <cuda_runtime.h>
#include <cstdint>
#include <cmath>

#define N_NODES 12500
#define N_EDGES 200000
#define OUT_ELEMS (N_NODES * 64)
#define N_TILES (N_EDGES / 16)        // 12500 tiles of 16 edges, exact
#define A_STRIDE 24                    // padded A row: h[16] | 1 | 0*7
#define THREADS 640
#define WPB 20                         // warps per block

// smem layout (floats)
#define BP_WORDS (4 * 16 * 32 * 12)    // 24576: fragment-packed B
#define SM_BP  0
#define SM_CS  BP_WORDS
#define CS_WARP 1632                   // 6*256 coeff + 64 sh + 16 scale + 16 dst
#define SM_BYTES ((SM_CS + WPB * CS_WARP) * 4)   // 228864 bytes

__device__ int   g_src[N_EDGES];
__device__ int   g_dst[N_EDGES];
__device__ float g_counts[N_NODES];        // after h_kernel: 1/max(count,1)
__device__ float g_h2[(size_t)N_EDGES * A_STRIDE];  // tf32 A rows
__device__ float g_Bpack[BP_WORDS];        // fragment-order packed B (tf32)
__device__ int   g_is64;

__device__ __forceinline__ float to_tf32(float x) {
    uint32_t u; asm("cvt.rna.tf32.f32 %0, %1;" : "=r"(u) : "f"(x));
    return __uint_as_float(u);
}

// m16n8k8 tf32 HMMA, D accumulates in place
__device__ __forceinline__ void mma8(float* d, const uint32_t* a, uint32_t b0, uint32_t b1) {
    asm volatile("mma.sync.aligned.m16n8k8.row.col.f32.tf32.tf32.f32 "
        "{%0,%1,%2,%3}, {%4,%5,%6,%7}, {%8,%9}, {%0,%1,%2,%3};"
        : "+f"(d[0]), "+f"(d[1]), "+f"(d[2]), "+f"(d[3])
        : "r"(a[0]), "r"(a[1]), "r"(a[2]), "r"(a[3]), "r"(b0), "r"(b1));
}

#define RED_V2(p, x, y) \
    asm volatile("red.global.add.v2.f32 [%0], {%1, %2};" \
        :: "l"(p), "f"(x), "f"(y) : "memory")

// k1: detect dtype, zero out/counts, build fragment-packed B
__global__ void zero_kernel(const unsigned* __restrict__ ei, float* __restrict__ out,
                            const float* __restrict__ w2, const float* __restrict__ b2) {
    int i = blockIdx.x * blockDim.x + threadIdx.x;
    if (i == 0) {
        int ok = 1;
        for (int j = 0; j < 128; j++) ok &= (ei[2 * j + 1] == 0u);
        g_is64 = ok;
    }
    if (i < OUT_ELEMS) out[i] = 0.f;
    if (i < N_NODES) g_counts[i] = 0.f;
    if (i < BP_WORDS) {
        int m = i % 12, lane = (i / 12) & 31, bu = i / (12 * 32);
        int s = m >> 2, r = m & 3;
        int col = (bu >> 4) * 256 + (bu & 15) * 16 + (lane >> 2) + ((r & 2) ? 8 : 0);
        int k = s * 8 + (lane & 3) + ((r & 1) ? 4 : 0);
        float v = (k < 16) ? w2[k * 1024 + col] : (k == 16 ? b2[col] : 0.f);
        g_Bpack[i] = to_tf32(v);
    }
}

// k2: edge_index -> int32, count dsts
__global__ void prep_kernel(const int* __restrict__ ei) {
    int i = blockIdx.x * blockDim.x + threadIdx.x;
    if (i < N_EDGES) {
        int s, d;
        if (g_is64) { s = ei[2 * i]; d = ei[2 * (N_EDGES + i)]; }
        else        { s = ei[i];     d = ei[N_EDGES + i]; }
        g_src[i] = s; g_dst[i] = d;
        atomicAdd(&g_counts[d], 1.f);
    }
}

// k3: A rows = [tf32(silu(ea@w1+b1)) | 1 | 0*7]; also inverts counts
__global__ void h_kernel(const float* __restrict__ ea,
                         const float* __restrict__ w1g,
                         const float* __restrict__ b1g) {
    __shared__ float sw[256], sb[16];
    if (threadIdx.x < 256) sw[threadIdx.x] = w1g[threadIdx.x];
    if (threadIdx.x < 16)  sb[threadIdx.x] = b1g[threadIdx.x];
    __syncthreads();
    int e = blockIdx.x * blockDim.x + threadIdx.x;
    if (e < N_NODES) g_counts[e] = 1.f / fmaxf(g_counts[e], 1.f);
    if (e >= N_EDGES) return;
    const float4* r = (const float4*)(ea + (size_t)e * 16);
    float4 v0 = r[0], v1 = r[1], v2 = r[2], v3 = r[3];
    float in[16] = {v0.x, v0.y, v0.z, v0.w, v1.x, v1.y, v1.z, v1.w,
                    v2.x, v2.y, v2.z, v2.w, v3.x, v3.y, v3.z, v3.w};
    float o[16];
    #pragma unroll
    for (int k = 0; k < 16; k++) {
        float t = sb[k];
        #pragma unroll
        for (int j = 0; j < 16; j++) t = fmaf(in[j], sw[j * 16 + k], t);
        o[k] = to_tf32(t / (1.f + __expf(-t)));
    }
    float4* dst = (float4*)(g_h2 + (size_t)e * A_STRIDE);
    dst[0] = make_float4(o[0], o[1], o[2], o[3]);
    dst[1] = make_float4(o[4], o[5], o[6], o[7]);
    dst[2] = make_float4(o[8], o[9], o[10], o[11]);
    dst[3] = make_float4(o[12], o[13], o[14], o[15]);
    dst[4] = make_float4(1.f, 0.f, 0.f, 0.f);
    dst[5] = make_float4(0.f, 0.f, 0.f, 0.f);
}

// ---------------------------------------------------------------------------
// k4: conv. One warp = 16 edges. W = A@B via m16n8k8 tf32 mma.sync with
// fragment-packed B. Coefficients stored pair-adjacent (edge g at slot 2g,
// edge g+8 at 2g+1) -> float2 LDS. out0 flushed early to cut reg pressure.
// ---------------------------------------------------------------------------
__global__ void __launch_bounds__(THREADS, 1) conv_kernel(
    const float*  __restrict__ node_attr,
    const float4* __restrict__ edge_sh4,
    float*        __restrict__ out)
{
    extern __shared__ float sm[];
    const int tid = threadIdx.x, lane = tid & 31, warp = tid >> 5;
    const int g = lane >> 2, tig = lane & 3;

    // stage fragment-packed B (96 KB)
    for (int i = tid; i < BP_WORDS / 4; i += THREADS)
        ((float4*)sm)[i] = ((const float4*)g_Bpack)[i];
    __syncthreads();

    float* cs = sm + SM_CS + warp * CS_WARP;
    const int eL = lane & 15, u0 = (lane >> 4) * 8;
    const int slot = 2 * (eL & 7) + (eL >> 3);    // pair-adjacent coeff slot
    const float alpha = 0.17677669529663688f;     // 1/sqrt(32)
    const float inv3  = 0.57735026918962576f;     // 1/sqrt(3)

    const uint32_t* Ag = (const uint32_t*)g_h2;
    const float4* Bp = (const float4*)sm + lane * 3;   // + (blk*16+u)*96

    for (int t = blockIdx.x * WPB + warp; t < N_TILES; t += gridDim.x * WPB) {
        const int e0 = t * 16;

        // ---- coefficient staging (warp-private smem, pair-adjacent) ----
        __syncwarp();
        {
            int eg = e0 + eL;
            int sn = g_src[eg];
            float4 sh = edge_sh4[eg];
            const float* na = node_attr + (size_t)sn * 64;
            #pragma unroll
            for (int i = 0; i < 8; i++) {
                int u = u0 + i;
                float x0 = na[u];
                float xa = na[16 + 3*u], xb = na[17 + 3*u], xc = na[18 + 3*u];
                cs[       u*16 + slot] = x0 * sh.x;                                 // c0
                cs[256  + u*16 + slot] = inv3 * (xa*sh.y + xb*sh.z + xc*sh.w);      // z
                cs[512  + u*16 + slot] = x0;                                        // x0
                cs[768  + u*16 + slot] = sh.x * xa;                                 // y0*x1a
                cs[1024 + u*16 + slot] = sh.x * xb;                                 // y0*x1b
                cs[1280 + u*16 + slot] = sh.x * xc;                                 // y0*x1c
            }
            if (u0 == 0) {
                ((float4*)(cs + 1536))[eL] = sh;
                int dn = g_dst[eg];
                cs[1600 + eL] = alpha * g_counts[dn];
                ((int*)(cs + 1616))[eL] = dn;
            }
        }
        __syncwarp();

        // ---- A fragments: 16 edges x 24 k, 3 k-steps ----
        uint32_t a[3][4];
        #pragma unroll
        for (int s = 0; s < 3; s++) {
            a[s][0] = Ag[(size_t)(e0 + g)     * A_STRIDE + s*8 + tig];
            a[s][1] = Ag[(size_t)(e0 + g + 8) * A_STRIDE + s*8 + tig];
            a[s][2] = Ag[(size_t)(e0 + g)     * A_STRIDE + s*8 + tig + 4];
            a[s][3] = Ag[(size_t)(e0 + g + 8) * A_STRIDE + s*8 + tig + 4];
        }

#define MMA_PAIR(BLK, U) \
        float d0[4] = {0.f,0.f,0.f,0.f}, d1[4] = {0.f,0.f,0.f,0.f}; \
        { const float4* bp = Bp + ((BLK)*16 + (U)) * 96; \
          _Pragma("unroll") \
          for (int s = 0; s < 3; s++) { \
            float4 bv = bp[s]; \
            mma8(d0, a[s], __float_as_uint(bv.x), __float_as_uint(bv.y)); \
            mma8(d1, a[s], __float_as_uint(bv.z), __float_as_uint(bv.w)); \
          } }

#define ACC1(ACC, CBASE, U) { \
        float2 cf = *(const float2*)(cs + (CBASE) + (U)*16 + 2*g); \
        ACC[0][0][0] += cf.x*d0[0]; ACC[0][0][1] += cf.x*d0[1]; \
        ACC[1][0][0] += cf.y*d0[2]; ACC[1][0][1] += cf.y*d0[3]; \
        ACC[0][1][0] += cf.x*d1[0]; ACC[0][1][1] += cf.x*d1[1]; \
        ACC[1][1][0] += cf.y*d1[2]; ACC[1][1][1] += cf.y*d1[3]; }

        // ---- out0 path: blocks 0 and 1, then flush (frees 8 regs) ----
        {
            float o0[2][2][2] = {};
            #pragma unroll 4
            for (int u = 0; u < 16; u++) { MMA_PAIR(0, u) ACC1(o0, 0,   u) }
            #pragma unroll 4
            for (int u = 0; u < 16; u++) { MMA_PAIR(1, u) ACC1(o0, 256, u) }
            #pragma unroll
            for (int r2 = 0; r2 < 2; r2++) {
                int e = g + r2 * 8;
                float sca = cs[1600 + e];
                float* o = out + (size_t)((int*)(cs + 1616))[e] * 64;
                RED_V2(o + 2*tig,     sca * o0[r2][0][0], sca * o0[r2][0][1]);
                RED_V2(o + 8 + 2*tig, sca * o0[r2][1][0], sca * o0[r2][1][1]);
            }
        }

        // ---- out1 path: blocks 2 and 3 ----
        float tAc[2][2][2] = {};
        float oA[2][2][2] = {}, oB[2][2][2] = {}, oC[2][2][2] = {};
        #pragma unroll 4
        for (int u = 0; u < 16; u++) { MMA_PAIR(2, u) ACC1(tAc, 512, u) }
        #pragma unroll 4
        for (int u = 0; u < 16; u++) { MMA_PAIR(3, u)
            ACC1(oA, 768, u) ACC1(oB, 1024, u) ACC1(oC, 1280, u) }
#undef MMA_PAIR
#undef ACC1

        #pragma unroll
        for (int r2 = 0; r2 < 2; r2++) {
            int e = g + r2 * 8;
            float4 sh = ((float4*)(cs + 1536))[e];
            float sca = cs[1600 + e];
            float* o = out + (size_t)((int*)(cs + 1616))[e] * 64;
            #pragma unroll
            for (int wh = 0; wh < 2; wh++) {
                // cols 16 + 24*wh + 6*tig .. +5  (w = wh*8 + 2*tig + {0,1})
                float* ob = o + 16 + 24*wh + 6*tig;
                float t0 = tAc[r2][wh][0], t1 = tAc[r2][wh][1];
                RED_V2(ob,     sca * (sh.y*t0 + oA[r2][wh][0]),
                               sca * (sh.z*t0 + oB[r2][wh][0]));
                RED_V2(ob + 2, sca * (sh.w*t0 + oC[r2][wh][0]),
                               sca * (sh.y*t1 + oA[r2][wh][1]));
                RED_V2(ob + 4, sca * (sh.z*t1 + oB[r2][wh][1]),
                               sca * (sh.w*t1 + oC[r2][wh][1]));
            }
        }
    }
}

extern "C" void kernel_launch(void* const* d_in, const int* in_sizes, int n_in,
                              void* d_out, int out_size) {
    const float* node_attr  = (const float*)d_in[0];
    const void*  edge_index = d_in[1];
    const float* edge_attr  = (const float*)d_in[2];
    const float* edge_sh    = (const float*)d_in[3];
    const float* w1 = (const float*)d_in[4];
    const float* b1 = (const float*)d_in[5];
    const float* w2 = (const float*)d_in[6];
    const float* b2 = (const float*)d_in[7];
    float* out = (float*)d_out;

    cudaFuncSetAttribute(conv_kernel, cudaFuncAttributeMaxDynamicSharedMemorySize, SM_BYTES);

    int smCount = 148;
    cudaDeviceGetAttribute(&smCount, cudaDevAttrMultiProcessorCount, 0);

    zero_kernel<<<(OUT_ELEMS + 255) / 256, 256>>>((const unsigned*)edge_index, out, w2, b2);
    prep_kernel<<<(N_EDGES + 255) / 256, 256>>>((const int*)edge_index);
    h_kernel<<<(N_EDGES + 255) / 256, 256>>>(edge_attr, w1, b1);
    conv_kernel<<<smCount, THREADS, SM_BYTES>>>(node_attr, (const float4*)edge_sh, out);
}